// round 1
// baseline (speedup 1.0000x reference)
#include <cuda_runtime.h>
#include <math.h>

// ---------------- problem constants ----------------
#define NVARD 600
#define NCD   1000
#define NEQD  150
#define HIDD  1024
#define BATCHD 1024
#define MLPOUTD 2200
#define GIND  4800
#define GOUTD 1600
#define MAXITERD 15
#define KKTN  750          // KKT size
#define GLD   1504         // augmented matrix width (750 + 750 + pad)
#define BLKD  150          // Gauss-Jordan block size
#define BILD  152          // small-block leading dim
#define OUT_TOTAL (BATCHD*NVARD + BATCHD + BATCHD + MAXITERD*BATCHD + MAXITERD*BATCHD)

// ---------------- device scratch ----------------
__device__ float g_inp[BATCHD*NVARD];
__device__ float g_h1[BATCHD*HIDD];
__device__ float g_h2[BATCHD*HIDD];
__device__ float g_nnout[BATCHD*MLPOUTD];
__device__ float g_hst[BATCHD*HIDD];
__device__ float g_lam[BATCHD*NVARD];
__device__ float g_lamnew[BATCHD*NVARD];
__device__ float g_s[BATCHD*NCD];
__device__ float g_snew[BATCHD*NCD];
__device__ float g_res[BATCHD*NCD];
__device__ float g_baug[BATCHD*NCD];
__device__ float g_u[BATCHD*NVARD];
__device__ float g_xi[BATCHD*NVARD];
__device__ float g_r[BATCHD*GIND];
__device__ float g_gi[BATCHD*3*HIDD];
__device__ float g_gh[BATCHD*3*HIDD];
__device__ float g_gout[BATCHD*GOUTD];
__device__ float g_G[KKTN*GLD];
__device__ float g_P[BLKD*GLD];
__device__ float g_Ucol[KKTN*BILD];
__device__ float g_Einv[BLKD*BILD];
__device__ float g_Ct[NVARD*NCD];
__device__ float g_v0[NVARD];
__device__ float g_negg[NVARD];
__device__ float g_prim[MAXITERD*BATCHD];
__device__ float g_fp[MAXITERD*BATCHD];
__device__ double g_sum2[2];

// ---------------- generic GEMM ----------------
// C = act( alpha * A @ op(B) + beta * Cin + bias )
// A: [M,K] row-major (lda). transB=0: B is [K,N] (ldb). transB=1: B is [N,K] (ldb).
// act: 0 none, 1 relu, 2 tanh, 3 dual-output: C = relu(bias - acc), C2 = relu(acc - bias)
#define BM 64
#define BN 64
#define BKK 16

__global__ void gemm_k(const float* __restrict__ A, const float* __restrict__ B,
                       float* __restrict__ C, float* __restrict__ C2,
                       const float* __restrict__ Cin, const float* __restrict__ bias,
                       int M, int N, int K, int lda, int ldb, int ldc, int ldcin,
                       int transB, float alpha, float beta, int act)
{
    __shared__ float As[BKK][BM];
    __shared__ float Bs[BKK][BN];
    const int tid = threadIdx.x;
    const int tx = tid & 15, ty = tid >> 4;
    const int m0 = blockIdx.y * BM, n0 = blockIdx.x * BN;
    float acc[4][4] = {};

    for (int kk = 0; kk < K; kk += BKK) {
#pragma unroll
        for (int i = 0; i < 4; i++) {
            int e = tid + i * 256;
            int m = e >> 4, k = e & 15;
            int gm = m0 + m, gk = kk + k;
            As[k][m] = (gm < M && gk < K) ? A[gm * lda + gk] : 0.f;
        }
        if (transB) {
#pragma unroll
            for (int i = 0; i < 4; i++) {
                int e = tid + i * 256;
                int n = e >> 4, k = e & 15;
                int gn = n0 + n, gk = kk + k;
                Bs[k][n] = (gn < N && gk < K) ? B[gn * ldb + gk] : 0.f;
            }
        } else {
#pragma unroll
            for (int i = 0; i < 4; i++) {
                int e = tid + i * 256;
                int k = e >> 6, n = e & 63;
                int gn = n0 + n, gk = kk + k;
                Bs[k][n] = (gn < N && gk < K) ? B[gk * ldb + gn] : 0.f;
            }
        }
        __syncthreads();
#pragma unroll
        for (int k = 0; k < BKK; k++) {
            float a0 = As[k][ty*4+0], a1 = As[k][ty*4+1], a2 = As[k][ty*4+2], a3 = As[k][ty*4+3];
            float b0 = Bs[k][tx*4+0], b1 = Bs[k][tx*4+1], b2 = Bs[k][tx*4+2], b3 = Bs[k][tx*4+3];
            acc[0][0] += a0*b0; acc[0][1] += a0*b1; acc[0][2] += a0*b2; acc[0][3] += a0*b3;
            acc[1][0] += a1*b0; acc[1][1] += a1*b1; acc[1][2] += a1*b2; acc[1][3] += a1*b3;
            acc[2][0] += a2*b0; acc[2][1] += a2*b1; acc[2][2] += a2*b2; acc[2][3] += a2*b3;
            acc[3][0] += a3*b0; acc[3][1] += a3*b1; acc[3][2] += a3*b2; acc[3][3] += a3*b3;
        }
        __syncthreads();
    }

#pragma unroll
    for (int i = 0; i < 4; i++) {
        int row = m0 + ty*4 + i;
        if (row >= M) continue;
#pragma unroll
        for (int j = 0; j < 4; j++) {
            int col = n0 + tx*4 + j;
            if (col >= N) continue;
            float v = alpha * acc[i][j];
            if (beta != 0.f) v += beta * Cin[row * ldcin + col];
            if (act == 3) {
                float cc = bias[col];
                C[row * ldc + col]  = fmaxf(cc - v, 0.f);
                C2[row * ldc + col] = fmaxf(v - cc, 0.f);
            } else {
                if (bias) v += bias[col];
                if (act == 1) v = fmaxf(v, 0.f);
                else if (act == 2) v = tanhf(v);
                C[row * ldc + col] = v;
            }
        }
    }
}

// ---------------- statistics / normalization ----------------
__global__ void stats_zero_k() { g_sum2[0] = 0.0; g_sum2[1] = 0.0; }

__global__ void stats_k(const float* __restrict__ x, int n) {
    float s = 0.f, ss = 0.f;
    for (int i = blockIdx.x * blockDim.x + threadIdx.x; i < n; i += gridDim.x * blockDim.x) {
        float v = x[i]; s += v; ss += v * v;
    }
    __shared__ float s1[256], s2[256];
    s1[threadIdx.x] = s; s2[threadIdx.x] = ss;
    __syncthreads();
    for (int o = 128; o > 0; o >>= 1) {
        if (threadIdx.x < o) { s1[threadIdx.x] += s1[threadIdx.x+o]; s2[threadIdx.x] += s2[threadIdx.x+o]; }
        __syncthreads();
    }
    if (threadIdx.x == 0) {
        atomicAdd(&g_sum2[0], (double)s1[0]);
        atomicAdd(&g_sum2[1], (double)s2[0]);
    }
}

__global__ void normalize_k(const float* __restrict__ x, int n) {
    double sum = g_sum2[0], sumsq = g_sum2[1];
    double mean = sum / n;
    double var = (sumsq - sum * sum / n) / (double)(n - 1);
    float istd = 1.0f / ((float)sqrt(var) + 1e-8f);
    float m = (float)mean;
    for (int i = blockIdx.x * blockDim.x + threadIdx.x; i < n; i += gridDim.x * blockDim.x)
        g_inp[i] = (x[i] - m) * istd;
}

// ---------------- small setup kernels ----------------
__global__ void split_nnout_k() {
    int idx = blockIdx.x * blockDim.x + threadIdx.x;
    int total = BATCHD * 1600;
    if (idx >= total) return;
    int b = idx / 1600, r = idx % 1600;
    if (r < NVARD) g_lam[b * NVARD + r] = g_nnout[b * MLPOUTD + NVARD + r];
    else {
        int j = r - NVARD;
        g_s[b * NCD + j] = fmaxf(g_nnout[b * MLPOUTD + 2 * NVARD + j], 0.f);
    }
}

__global__ void transpose_C_k(const float* __restrict__ Cm) {
    int idx = blockIdx.x * blockDim.x + threadIdx.x;
    if (idx >= NVARD * NCD) return;
    int i = idx / NCD, k = idx % NCD;
    g_Ct[i * NCD + k] = Cm[k * NVARD + i];
}

__global__ void negg_k(const float* __restrict__ gv) {
    int j = blockIdx.x * blockDim.x + threadIdx.x;
    if (j < NVARD) g_negg[j] = -gv[j];
}

__global__ void init_G_k() {
    int idx = blockIdx.x * blockDim.x + threadIdx.x;
    if (idx >= KKTN * GLD) return;
    int r = idx / GLD, c = idx % GLD;
    float v = 0.f;
    if (c >= 750) {
        if (c - 750 == r) v = 1.f;             // right half: identity
    } else if (r >= 600 && c < 600) {          // A_eq
        int rr = r - 600, t = rr / 3, i = rr % 3;
        if (c / 12 == t && (c % 12) % 3 == i) v = 1.f;
    } else if (r < 600 && c >= 600) {          // A_eq^T
        int cc = c - 600, t = cc / 3, i = cc % 3;
        if (r / 12 == t && (r % 12) % 3 == i) v = 1.f;
    }
    g_G[idx] = v;   // top-left (cost) is overwritten by GEMM afterward
}

__global__ void v0_k() {
    int j = blockIdx.x * blockDim.x + threadIdx.x;
    if (j >= NVARD) return;
    float beq = 30.0f * 9.81f;
    float acc = 0.f;
    for (int t = 0; t < 50; t++) acc += g_G[j * GLD + 750 + 600 + 3 * t + 2];
    g_v0[j] = beq * acc;
}

// ---------------- blocked Gauss-Jordan helpers ----------------
__global__ void copy_cols_k(int kb) {
    int idx = blockIdx.x * blockDim.x + threadIdx.x;
    if (idx >= KKTN * BLKD) return;
    int r = idx / BLKD, j = idx % BLKD;
    g_Ucol[r * BILD + j] = g_G[r * GLD + kb * BLKD + j];
}

// in-place Gauss-Jordan inverse of the pivot block (150x150), unpivoted
__global__ void inv_block_k(int kb) {
    extern __shared__ float s[];           // BLKD x BILD
    const int n = BLKD, ld = BILD;
    int tid = threadIdx.x, nt = blockDim.x;
    for (int e = tid; e < n * n; e += nt)
        s[(e / n) * ld + (e % n)] = g_Ucol[(kb * BLKD + e / n) * BILD + (e % n)];
    __shared__ float fcol[BLKD];
    __shared__ float s_ipiv;
    __syncthreads();
    for (int p = 0; p < n; p++) {
        if (tid == 0) s_ipiv = 1.0f / s[p * ld + p];
        __syncthreads();
        float ipiv = s_ipiv;
        for (int j = tid; j < n; j += nt) if (j != p) s[p * ld + j] *= ipiv;
        for (int r = tid; r < n; r += nt) fcol[r] = (r == p) ? 0.f : s[r * ld + p];
        __syncthreads();
        for (int e = tid; e < n * n; e += nt) {
            int r = e / n, j = e % n;
            if (r != p && j != p) s[r * ld + j] -= fcol[r] * s[p * ld + j];
        }
        __syncthreads();
        for (int r = tid; r < n; r += nt) {
            if (r == p) s[p * ld + p] = ipiv;
            else s[r * ld + p] = -fcol[r] * ipiv;
        }
        __syncthreads();
    }
    for (int e = tid; e < n * n; e += nt)
        g_Einv[(e / n) * BILD + (e % n)] = s[(e / n) * ld + (e % n)];
}

__global__ void writeback_k(int kb) {
    int idx = blockIdx.x * blockDim.x + threadIdx.x;
    if (idx >= BLKD * GLD) return;
    int r = idx / GLD, j = idx % GLD;
    g_G[(kb * BLKD + r) * GLD + j] = g_P[idx];
    if (j < BILD) g_Ucol[(kb * BLKD + r) * BILD + j] = 0.f;
}

// ---------------- iteration elementwise kernels ----------------
__global__ void baug_k(const float* __restrict__ cvec) {
    int idx = blockIdx.x * blockDim.x + threadIdx.x;
    if (idx >= BATCHD * NCD) return;
    int j = idx % NCD;
    g_baug[idx] = cvec[j] - g_s[idx];
}

__global__ void rownorm_k(const float* __restrict__ v, int ncols, float* __restrict__ out) {
    int b = blockIdx.x;
    float acc = 0.f;
    for (int j = threadIdx.x; j < ncols; j += blockDim.x) {
        float t = v[b * ncols + j]; acc += t * t;
    }
    __shared__ float sm[256];
    sm[threadIdx.x] = acc; __syncthreads();
    for (int o = 128; o > 0; o >>= 1) {
        if (threadIdx.x < o) sm[threadIdx.x] += sm[threadIdx.x + o];
        __syncthreads();
    }
    if (threadIdx.x == 0) out[b] = sqrtf(sm[0]);
}

__global__ void concat_r_k() {
    int idx = blockIdx.x * blockDim.x + threadIdx.x;
    if (idx >= BATCHD * GIND) return;
    int b = idx / GIND, q = idx % GIND;
    float v;
    if (q < 1000)       v = g_s[b * NCD + q];
    else if (q < 1600)  v = g_lam[b * NVARD + (q - 1000)];
    else if (q < 2600)  v = g_snew[b * NCD + (q - 1600)];
    else if (q < 3200)  v = g_lamnew[b * NVARD + (q - 2600)];
    else if (q < 4200)  v = g_snew[b * NCD + (q - 3200)] - g_s[b * NCD + (q - 3200)];
    else                v = g_lamnew[b * NVARD + (q - 4200)] - g_lam[b * NVARD + (q - 4200)];
    g_r[idx] = v;
}

__device__ __forceinline__ float sigmoidf(float x) { return 1.0f / (1.0f + expf(-x)); }

__global__ void gru_k() {
    int idx = blockIdx.x * blockDim.x + threadIdx.x;
    if (idx >= BATCHD * HIDD) return;
    int b = idx >> 10, j = idx & 1023;
    int base = b * 3 * HIDD + j;
    float ir = g_gi[base], iz = g_gi[base + HIDD], in_ = g_gi[base + 2 * HIDD];
    float hr = g_gh[base], hz = g_gh[base + HIDD], hn = g_gh[base + 2 * HIDD];
    float rg = sigmoidf(ir + hr);
    float z  = sigmoidf(iz + hz);
    float n  = tanhf(in_ + rg * hn);
    float h  = g_hst[idx];
    g_hst[idx] = (1.f - z) * n + z * h;
}

__global__ void finalize_k(int t) {
    int b = blockIdx.x;
    float accs = 0.f, accl = 0.f;
    for (int j = threadIdx.x; j < GOUTD; j += blockDim.x) {
        float go = g_gout[b * GOUTD + j];
        if (j < NCD) {
            float sf = fmaxf(g_snew[b * NCD + j] + go, 0.f);
            float d = sf - g_s[b * NCD + j];
            accs += d * d;
            g_s[b * NCD + j] = sf;
        } else {
            int j2 = j - NCD;
            float lf = g_lamnew[b * NVARD + j2] + go;
            float d = lf - g_lam[b * NVARD + j2];
            accl += d * d;
            g_lam[b * NVARD + j2] = lf;
        }
    }
    __shared__ float sm1[256], sm2[256];
    sm1[threadIdx.x] = accs; sm2[threadIdx.x] = accl;
    __syncthreads();
    for (int o = 128; o > 0; o >>= 1) {
        if (threadIdx.x < o) { sm1[threadIdx.x] += sm1[threadIdx.x+o]; sm2[threadIdx.x] += sm2[threadIdx.x+o]; }
        __syncthreads();
    }
    if (threadIdx.x == 0)
        g_fp[t * BATCHD + b] = sqrtf(sm2[0]) + sqrtf(sm1[0]);
}

// ---------------- output assembly ----------------
__global__ void output_k(float* __restrict__ out) {
    int idx = blockIdx.x * blockDim.x + threadIdx.x;
    if (idx >= OUT_TOTAL) return;
    const int XI_END = BATCHD * NVARD;            // 614400
    const int AFP_END = XI_END + BATCHD;          // 615424
    const int APR_END = AFP_END + BATCHD;         // 616448
    const int PH_END = APR_END + MAXITERD * BATCHD; // 631808
    if (idx < XI_END) out[idx] = g_xi[idx];
    else if (idx < AFP_END) {
        int b = idx - XI_END;
        float a = 0.f;
        for (int t = 0; t < MAXITERD; t++) a += g_fp[t * BATCHD + b];
        out[idx] = a / (float)MAXITERD;
    } else if (idx < APR_END) {
        int b = idx - AFP_END;
        float a = 0.f;
        for (int t = 0; t < MAXITERD; t++) a += g_prim[t * BATCHD + b];
        out[idx] = a / (float)MAXITERD;
    } else if (idx < PH_END) out[idx] = g_prim[idx - APR_END];
    else out[idx] = g_fp[idx - PH_END];
}

// ---------------- host side ----------------
static void gemm(const float* A, const float* B, float* C, float* C2,
                 const float* Cin, const float* bias,
                 int M, int N, int K, int lda, int ldb, int ldc, int ldcin,
                 int transB, float alpha, float beta, int act)
{
    dim3 grid((N + BN - 1) / BN, (M + BM - 1) / BM);
    gemm_k<<<grid, 256>>>(A, B, C, C2, Cin, bias, M, N, K, lda, ldb, ldc, ldcin,
                          transB, alpha, beta, act);
}

static inline int ceil_div(int a, int b) { return (a + b - 1) / b; }

extern "C" void kernel_launch(void* const* d_in, const int* in_sizes, int n_in,
                              void* d_out, int out_size) {
    const float* X    = (const float*)d_in[0];
    const float* Hm   = (const float*)d_in[1];
    const float* gv   = (const float*)d_in[2];
    const float* Cm   = (const float*)d_in[3];
    const float* cvec = (const float*)d_in[4];
    const float* W1   = (const float*)d_in[5];
    const float* b1   = (const float*)d_in[6];
    const float* W2   = (const float*)d_in[7];
    const float* b2   = (const float*)d_in[8];
    const float* W3   = (const float*)d_in[9];
    const float* b3   = (const float*)d_in[10];
    const float* Wg   = (const float*)d_in[11];
    const float* bg   = (const float*)d_in[12];
    const float* W_ih = (const float*)d_in[13];
    const float* W_hh = (const float*)d_in[14];
    const float* b_ih = (const float*)d_in[15];
    const float* b_hh = (const float*)d_in[16];
    const float* W_out= (const float*)d_in[17];
    const float* b_out= (const float*)d_in[18];
    float* out = (float*)d_out;

    // resolve device scratch addresses
    float *inp, *h1, *h2, *nnout, *hst, *lam, *lamnew, *s, *snew, *res, *baug, *u, *xi,
          *r, *gi, *gh, *gout, *G, *P, *Ucol, *Einv, *Ct, *v0, *negg, *prim, *fp;
    cudaGetSymbolAddress((void**)&inp, g_inp);
    cudaGetSymbolAddress((void**)&h1, g_h1);
    cudaGetSymbolAddress((void**)&h2, g_h2);
    cudaGetSymbolAddress((void**)&nnout, g_nnout);
    cudaGetSymbolAddress((void**)&hst, g_hst);
    cudaGetSymbolAddress((void**)&lam, g_lam);
    cudaGetSymbolAddress((void**)&lamnew, g_lamnew);
    cudaGetSymbolAddress((void**)&s, g_s);
    cudaGetSymbolAddress((void**)&snew, g_snew);
    cudaGetSymbolAddress((void**)&res, g_res);
    cudaGetSymbolAddress((void**)&baug, g_baug);
    cudaGetSymbolAddress((void**)&u, g_u);
    cudaGetSymbolAddress((void**)&xi, g_xi);
    cudaGetSymbolAddress((void**)&r, g_r);
    cudaGetSymbolAddress((void**)&gi, g_gi);
    cudaGetSymbolAddress((void**)&gh, g_gh);
    cudaGetSymbolAddress((void**)&gout, g_gout);
    cudaGetSymbolAddress((void**)&G, g_G);
    cudaGetSymbolAddress((void**)&P, g_P);
    cudaGetSymbolAddress((void**)&Ucol, g_Ucol);
    cudaGetSymbolAddress((void**)&Einv, g_Einv);
    cudaGetSymbolAddress((void**)&Ct, g_Ct);
    cudaGetSymbolAddress((void**)&v0, g_v0);
    cudaGetSymbolAddress((void**)&negg, g_negg);
    cudaGetSymbolAddress((void**)&prim, g_prim);
    cudaGetSymbolAddress((void**)&fp, g_fp);

    cudaFuncSetAttribute(inv_block_k, cudaFuncAttributeMaxDynamicSharedMemorySize,
                         BLKD * BILD * (int)sizeof(float));

    const int TPB = 256;
    const int NTOT = BATCHD * NVARD;

    // ---- input normalization (global mean/std, ddof=1) ----
    stats_zero_k<<<1, 1>>>();
    stats_k<<<512, TPB>>>(X, NTOT);
    normalize_k<<<ceil_div(NTOT, TPB), TPB>>>(X, NTOT);

    // ---- MLP warm start ----
    gemm(inp, W1, h1, nullptr, nullptr, b1, BATCHD, HIDD, NVARD, NVARD, NVARD, HIDD, 0, 1, 1.f, 0.f, 1);
    gemm(h1, W2, h2, nullptr, nullptr, b2, BATCHD, HIDD, HIDD, HIDD, HIDD, HIDD, 0, 1, 1.f, 0.f, 1);
    gemm(h2, W3, nnout, nullptr, nullptr, b3, BATCHD, MLPOUTD, HIDD, HIDD, HIDD, MLPOUTD, 0, 1, 1.f, 0.f, 0);
    split_nnout_k<<<ceil_div(BATCHD * 1600, TPB), TPB>>>();
    gemm(inp, Wg, hst, nullptr, nullptr, bg, BATCHD, HIDD, NVARD, NVARD, NVARD, HIDD, 0, 1, 1.f, 0.f, 2);

    // ---- KKT build + blocked Gauss-Jordan inverse ----
    transpose_C_k<<<ceil_div(NVARD * NCD, TPB), TPB>>>(Cm);
    negg_k<<<ceil_div(NVARD, TPB), TPB>>>(gv);
    init_G_k<<<ceil_div(KKTN * GLD, TPB), TPB>>>();
    // top-left = H + C^T C
    gemm(Ct, Ct, G, nullptr, Hm, nullptr, NVARD, NVARD, NCD, NCD, NCD, GLD, NVARD, 1, 1.f, 1.f, 0);
    for (int kb = 0; kb < KKTN / BLKD; kb++) {
        copy_cols_k<<<ceil_div(KKTN * BLKD, TPB), TPB>>>(kb);
        inv_block_k<<<1, 512, BLKD * BILD * sizeof(float)>>>(kb);
        gemm(Einv, G + kb * BLKD * GLD, P, nullptr, nullptr, nullptr,
             BLKD, GLD, BLKD, BILD, GLD, GLD, 0, 0, 1.f, 0.f, 0);
        writeback_k<<<ceil_div(BLKD * GLD, TPB), TPB>>>(kb);
        gemm(Ucol, P, G, nullptr, G, nullptr,
             KKTN, GLD, BLKD, BILD, GLD, GLD, GLD, 0, -1.f, 1.f, 0);
    }
    v0_k<<<ceil_div(NVARD, TPB), TPB>>>();

    const float* Minv = G + 750;   // Q_inv[:, :] at ld GLD; cols 750.. are the inverse

    // ---- 15 fixed-point iterations ----
    for (int t = 0; t < MAXITERD; t++) {
        baug_k<<<ceil_div(BATCHD * NCD, TPB), TPB>>>(cvec);
        // u = (c - s) @ C + lam - g      ( = -lincost )
        gemm(baug, Cm, u, nullptr, lam, negg, BATCHD, NVARD, NCD, NCD, NVARD, NVARD, NVARD, 0, 1.f, 1.f, 0);
        // xi = u @ M + v0
        gemm(u, Minv, xi, nullptr, nullptr, v0, BATCHD, NVARD, NVARD, NVARD, GLD, NVARD, 0, 0, 1.f, 0.f, 0);
        // Cx = xi @ C^T ; s_new = relu(c - Cx), res = relu(Cx - c)
        gemm(xi, Cm, snew, res, nullptr, cvec, BATCHD, NCD, NVARD, NVARD, NVARD, NCD, 0, 1, 1.f, 0.f, 3);
        rownorm_k<<<BATCHD, 256>>>(res, NCD, prim + t * BATCHD);
        // lam_new = lam - res @ C
        gemm(res, Cm, lamnew, nullptr, lam, nullptr, BATCHD, NVARD, NCD, NCD, NVARD, NVARD, NVARD, 0, -1.f, 1.f, 0);
        concat_r_k<<<ceil_div(BATCHD * GIND, TPB), TPB>>>();
        // GRU gates
        gemm(r, W_ih, gi, nullptr, nullptr, b_ih, BATCHD, 3 * HIDD, GIND, GIND, GIND, 3 * HIDD, 0, 1, 1.f, 0.f, 0);
        gemm(hst, W_hh, gh, nullptr, nullptr, b_hh, BATCHD, 3 * HIDD, HIDD, HIDD, HIDD, 3 * HIDD, 0, 1, 1.f, 0.f, 0);
        gru_k<<<ceil_div(BATCHD * HIDD, TPB), TPB>>>();
        // output head
        gemm(hst, W_out, gout, nullptr, nullptr, b_out, BATCHD, GOUTD, HIDD, HIDD, HIDD, GOUTD, 0, 1, 1.f, 0.f, 0);
        finalize_k<<<BATCHD, 256>>>(t);
    }

    output_k<<<ceil_div(OUT_TOTAL, TPB), TPB>>>(out);
    (void)in_sizes; (void)n_in; (void)out_size;
}

// round 2
// speedup vs baseline: 1.5102x; 1.5102x over previous
#include <cuda_runtime.h>
#include <math.h>
#include <stdint.h>

// ---------------- problem constants ----------------
#define NVARD 600
#define NCD   1000
#define NEQD  150
#define HIDD  1024
#define BATCHD 1024
#define MLPOUTD 2200
#define GIND  4800
#define GOUTD 1600
#define MAXITERD 15
#define KKTN  750
#define GLD   1504
#define BLKD  150
#define BILD  152
#define OUT_TOTAL (BATCHD*NVARD + BATCHD + BATCHD + MAXITERD*BATCHD + MAXITERD*BATCHD)

// ---------------- device scratch ----------------
__device__ float g_inp[BATCHD*NVARD];
__device__ float g_h1[BATCHD*HIDD];
__device__ float g_h2[BATCHD*HIDD];
__device__ float g_nnout[BATCHD*MLPOUTD];
__device__ float g_hst[BATCHD*HIDD];
__device__ float g_lam[BATCHD*NVARD];
__device__ float g_lamnew[BATCHD*NVARD];
__device__ float g_s[BATCHD*NCD];
__device__ float g_snew[BATCHD*NCD];
__device__ float g_res[BATCHD*NCD];
__device__ float g_baug[BATCHD*NCD];
__device__ float g_u[BATCHD*NVARD];
__device__ float g_xi[BATCHD*NVARD];
__device__ float g_r[BATCHD*GIND];
__device__ float g_gi[BATCHD*3*HIDD];
__device__ float g_gh[BATCHD*3*HIDD];
__device__ float g_gout[BATCHD*GOUTD];
__device__ float g_G[KKTN*GLD];
__device__ float g_P[BLKD*GLD];
__device__ float g_Ucol[KKTN*BILD];
__device__ float g_Einv[BLKD*BILD];
__device__ float g_Ct[NVARD*NCD];
__device__ float g_v0[NVARD];
__device__ float g_negg[NVARD];
__device__ float g_prim[MAXITERD*BATCHD];
__device__ float g_fp[MAXITERD*BATCHD];
__device__ double g_sum2[2];

// ===================================================================
// Tensor-core GEMM: 3xTF32 (fp32-accurate) via mma.sync.m16n8k8
// C = act( alpha * A @ op(B) + beta * Cin + bias )
// act: 0 none, 1 relu, 2 tanh, 3 dual: C=relu(bias-acc), C2=relu(acc-bias)
// ===================================================================

__device__ __forceinline__ void tf32_split(float x, uint32_t& hi, uint32_t& lo) {
    uint32_t h;
    asm("cvt.rna.tf32.f32 %0, %1;" : "=r"(h) : "f"(x));
    float r = x - __uint_as_float(h);
    uint32_t l;
    asm("cvt.rna.tf32.f32 %0, %1;" : "=r"(l) : "f"(r));
    hi = h; lo = l;
}

#define MMA_TF32(ac, a, b) \
    asm volatile("mma.sync.aligned.m16n8k8.row.col.f32.tf32.tf32.f32 " \
                 "{%0,%1,%2,%3},{%4,%5,%6,%7},{%8,%9},{%0,%1,%2,%3};" \
                 : "+f"(ac[0]), "+f"(ac[1]), "+f"(ac[2]), "+f"(ac[3]) \
                 : "r"(a[0]), "r"(a[1]), "r"(a[2]), "r"(a[3]), "r"(b[0]), "r"(b[1]))

template<int TBM, int TBN>
__global__ void __launch_bounds__(256)
gemm_tc_k(const float* __restrict__ A, const float* __restrict__ B,
          float* __restrict__ C, float* __restrict__ C2,
          const float* __restrict__ Cin, const float* __restrict__ bias,
          int M, int N, int K, int lda, int ldb, int ldc, int ldcin,
          int transB, float alpha, float beta, int act)
{
    constexpr int WM = TBM / 2;     // warp tile M (2 warp-rows)
    constexpr int WN = TBN / 4;     // warp tile N (4 warp-cols)
    constexpr int MM = WM / 16;     // mma tiles per warp, M
    constexpr int NN = WN / 8;      // mma tiles per warp, N
    constexpr int APT = TBM * 16 / 256;   // A elems per thread per chunk
    constexpr int BPT = TBN * 16 / 256;

    __shared__ float As[2][16][TBM + 4];
    __shared__ float Bs[2][16][TBN + 4];

    const int tid = threadIdx.x;
    const int wid = tid >> 5;
    const int lane = tid & 31;
    const int lr = lane >> 2;   // 0..7
    const int lc = lane & 3;    // 0..3
    const int warp_m = wid >> 2;
    const int warp_n = wid & 3;
    const int m0 = blockIdx.y * TBM;
    const int n0 = blockIdx.x * TBN;

    float acc[MM][NN][4];
#pragma unroll
    for (int i = 0; i < MM; i++)
#pragma unroll
        for (int j = 0; j < NN; j++)
#pragma unroll
            for (int q = 0; q < 4; q++) acc[i][j][q] = 0.f;

    const int nchunks = (K + 15) / 16;

    float ra[APT], rb[BPT];

    // ---- prologue: load chunk 0 ----
    {
        const int kk = 0;
#pragma unroll
        for (int i = 0; i < APT; i++) {
            int e = tid + i * 256;
            int m = e >> 4, k = e & 15;
            int gm = m0 + m, gk = kk + k;
            ra[i] = (gm < M && gk < K) ? A[gm * lda + gk] : 0.f;
        }
        if (transB) {
#pragma unroll
            for (int i = 0; i < BPT; i++) {
                int e = tid + i * 256;
                int n = e >> 4, k = e & 15;
                int gn = n0 + n, gk = kk + k;
                rb[i] = (gn < N && gk < K) ? B[gn * ldb + gk] : 0.f;
            }
        } else {
#pragma unroll
            for (int i = 0; i < BPT; i++) {
                int e = tid + i * 256;
                int k = e / TBN, n = e & (TBN - 1);
                int gn = n0 + n, gk = kk + k;
                rb[i] = (gn < N && gk < K) ? B[gk * ldb + gn] : 0.f;
            }
        }
#pragma unroll
        for (int i = 0; i < APT; i++) {
            int e = tid + i * 256;
            As[0][e & 15][e >> 4] = ra[i];
        }
        if (transB) {
#pragma unroll
            for (int i = 0; i < BPT; i++) {
                int e = tid + i * 256;
                Bs[0][e & 15][e >> 4] = rb[i];
            }
        } else {
#pragma unroll
            for (int i = 0; i < BPT; i++) {
                int e = tid + i * 256;
                Bs[0][e / TBN][e & (TBN - 1)] = rb[i];
            }
        }
        __syncthreads();
    }

    for (int ch = 0; ch < nchunks; ch++) {
        const int cur = ch & 1;
        const bool have_next = (ch + 1 < nchunks);

        // ---- prefetch next chunk into registers ----
        if (have_next) {
            const int kk = (ch + 1) * 16;
#pragma unroll
            for (int i = 0; i < APT; i++) {
                int e = tid + i * 256;
                int m = e >> 4, k = e & 15;
                int gm = m0 + m, gk = kk + k;
                ra[i] = (gm < M && gk < K) ? A[gm * lda + gk] : 0.f;
            }
            if (transB) {
#pragma unroll
                for (int i = 0; i < BPT; i++) {
                    int e = tid + i * 256;
                    int n = e >> 4, k = e & 15;
                    int gn = n0 + n, gk = kk + k;
                    rb[i] = (gn < N && gk < K) ? B[gn * ldb + gk] : 0.f;
                }
            } else {
#pragma unroll
                for (int i = 0; i < BPT; i++) {
                    int e = tid + i * 256;
                    int k = e / TBN, n = e & (TBN - 1);
                    int gn = n0 + n, gk = kk + k;
                    rb[i] = (gn < N && gk < K) ? B[gk * ldb + gn] : 0.f;
                }
            }
        }

        // ---- compute on current buffer ----
#pragma unroll
        for (int kb = 0; kb < 16; kb += 8) {
            uint32_t ahi[MM][4], alo[MM][4];
            uint32_t bhi[NN][2], blo[NN][2];
#pragma unroll
            for (int mm = 0; mm < MM; mm++) {
                int mrow = warp_m * WM + mm * 16 + lr;
                float x0 = As[cur][kb + lc][mrow];
                float x1 = As[cur][kb + lc][mrow + 8];
                float x2 = As[cur][kb + 4 + lc][mrow];
                float x3 = As[cur][kb + 4 + lc][mrow + 8];
                tf32_split(x0, ahi[mm][0], alo[mm][0]);
                tf32_split(x1, ahi[mm][1], alo[mm][1]);
                tf32_split(x2, ahi[mm][2], alo[mm][2]);
                tf32_split(x3, ahi[mm][3], alo[mm][3]);
            }
#pragma unroll
            for (int nn = 0; nn < NN; nn++) {
                int ncol = warp_n * WN + nn * 8 + lr;
                float y0 = Bs[cur][kb + lc][ncol];
                float y1 = Bs[cur][kb + 4 + lc][ncol];
                tf32_split(y0, bhi[nn][0], blo[nn][0]);
                tf32_split(y1, bhi[nn][1], blo[nn][1]);
            }
#pragma unroll
            for (int mm = 0; mm < MM; mm++) {
#pragma unroll
                for (int nn = 0; nn < NN; nn++) {
                    MMA_TF32(acc[mm][nn], alo[mm], bhi[nn]);
                    MMA_TF32(acc[mm][nn], ahi[mm], blo[nn]);
                    MMA_TF32(acc[mm][nn], ahi[mm], bhi[nn]);
                }
            }
        }

        // ---- store prefetched regs into the other buffer ----
        if (have_next) {
            const int nxt = cur ^ 1;
#pragma unroll
            for (int i = 0; i < APT; i++) {
                int e = tid + i * 256;
                As[nxt][e & 15][e >> 4] = ra[i];
            }
            if (transB) {
#pragma unroll
                for (int i = 0; i < BPT; i++) {
                    int e = tid + i * 256;
                    Bs[nxt][e & 15][e >> 4] = rb[i];
                }
            } else {
#pragma unroll
                for (int i = 0; i < BPT; i++) {
                    int e = tid + i * 256;
                    Bs[nxt][e / TBN][e & (TBN - 1)] = rb[i];
                }
            }
        }
        __syncthreads();
    }

    // ---- epilogue ----
#pragma unroll
    for (int mm = 0; mm < MM; mm++) {
        int r0 = m0 + warp_m * WM + mm * 16 + lr;
#pragma unroll
        for (int nn = 0; nn < NN; nn++) {
            int c0 = n0 + warp_n * WN + nn * 8 + lc * 2;
#pragma unroll
            for (int q = 0; q < 4; q++) {
                int row = r0 + (q >> 1) * 8;
                int col = c0 + (q & 1);
                if (row >= M || col >= N) continue;
                float v = alpha * acc[mm][nn][q];
                if (beta != 0.f) v += beta * Cin[row * ldcin + col];
                if (act == 3) {
                    float cc = bias[col];
                    C[row * ldc + col]  = fmaxf(cc - v, 0.f);
                    C2[row * ldc + col] = fmaxf(v - cc, 0.f);
                } else {
                    if (bias) v += bias[col];
                    if (act == 1) v = fmaxf(v, 0.f);
                    else if (act == 2) v = tanhf(v);
                    C[row * ldc + col] = v;
                }
            }
        }
    }
}

// ---------------- fp32 SIMT GEMM (kept for KKT inverse pipeline) --------
#define BM 64
#define BN 64
#define BKK 16

__global__ void gemm_k(const float* __restrict__ A, const float* __restrict__ B,
                       float* __restrict__ C, float* __restrict__ C2,
                       const float* __restrict__ Cin, const float* __restrict__ bias,
                       int M, int N, int K, int lda, int ldb, int ldc, int ldcin,
                       int transB, float alpha, float beta, int act)
{
    __shared__ float As[BKK][BM];
    __shared__ float Bs[BKK][BN];
    const int tid = threadIdx.x;
    const int tx = tid & 15, ty = tid >> 4;
    const int m0 = blockIdx.y * BM, n0 = blockIdx.x * BN;
    float acc[4][4] = {};

    for (int kk = 0; kk < K; kk += BKK) {
#pragma unroll
        for (int i = 0; i < 4; i++) {
            int e = tid + i * 256;
            int m = e >> 4, k = e & 15;
            int gm = m0 + m, gk = kk + k;
            As[k][m] = (gm < M && gk < K) ? A[gm * lda + gk] : 0.f;
        }
        if (transB) {
#pragma unroll
            for (int i = 0; i < 4; i++) {
                int e = tid + i * 256;
                int n = e >> 4, k = e & 15;
                int gn = n0 + n, gk = kk + k;
                Bs[k][n] = (gn < N && gk < K) ? B[gn * ldb + gk] : 0.f;
            }
        } else {
#pragma unroll
            for (int i = 0; i < 4; i++) {
                int e = tid + i * 256;
                int k = e >> 6, n = e & 63;
                int gn = n0 + n, gk = kk + k;
                Bs[k][n] = (gn < N && gk < K) ? B[gk * ldb + gn] : 0.f;
            }
        }
        __syncthreads();
#pragma unroll
        for (int k = 0; k < BKK; k++) {
            float a0 = As[k][ty*4+0], a1 = As[k][ty*4+1], a2 = As[k][ty*4+2], a3 = As[k][ty*4+3];
            float b0 = Bs[k][tx*4+0], b1 = Bs[k][tx*4+1], b2 = Bs[k][tx*4+2], b3 = Bs[k][tx*4+3];
            acc[0][0] += a0*b0; acc[0][1] += a0*b1; acc[0][2] += a0*b2; acc[0][3] += a0*b3;
            acc[1][0] += a1*b0; acc[1][1] += a1*b1; acc[1][2] += a1*b2; acc[1][3] += a1*b3;
            acc[2][0] += a2*b0; acc[2][1] += a2*b1; acc[2][2] += a2*b2; acc[2][3] += a2*b3;
            acc[3][0] += a3*b0; acc[3][1] += a3*b1; acc[3][2] += a3*b2; acc[3][3] += a3*b3;
        }
        __syncthreads();
    }

#pragma unroll
    for (int i = 0; i < 4; i++) {
        int row = m0 + ty*4 + i;
        if (row >= M) continue;
#pragma unroll
        for (int j = 0; j < 4; j++) {
            int col = n0 + tx*4 + j;
            if (col >= N) continue;
            float v = alpha * acc[i][j];
            if (beta != 0.f) v += beta * Cin[row * ldcin + col];
            if (act == 3) {
                float cc = bias[col];
                C[row * ldc + col]  = fmaxf(cc - v, 0.f);
                C2[row * ldc + col] = fmaxf(v - cc, 0.f);
            } else {
                if (bias) v += bias[col];
                if (act == 1) v = fmaxf(v, 0.f);
                else if (act == 2) v = tanhf(v);
                C[row * ldc + col] = v;
            }
        }
    }
}

// ---------------- statistics / normalization ----------------
__global__ void stats_zero_k() { g_sum2[0] = 0.0; g_sum2[1] = 0.0; }

__global__ void stats_k(const float* __restrict__ x, int n) {
    float s = 0.f, ss = 0.f;
    for (int i = blockIdx.x * blockDim.x + threadIdx.x; i < n; i += gridDim.x * blockDim.x) {
        float v = x[i]; s += v; ss += v * v;
    }
    __shared__ float s1[256], s2[256];
    s1[threadIdx.x] = s; s2[threadIdx.x] = ss;
    __syncthreads();
    for (int o = 128; o > 0; o >>= 1) {
        if (threadIdx.x < o) { s1[threadIdx.x] += s1[threadIdx.x+o]; s2[threadIdx.x] += s2[threadIdx.x+o]; }
        __syncthreads();
    }
    if (threadIdx.x == 0) {
        atomicAdd(&g_sum2[0], (double)s1[0]);
        atomicAdd(&g_sum2[1], (double)s2[0]);
    }
}

__global__ void normalize_k(const float* __restrict__ x, int n) {
    double sum = g_sum2[0], sumsq = g_sum2[1];
    double mean = sum / n;
    double var = (sumsq - sum * sum / n) / (double)(n - 1);
    float istd = 1.0f / ((float)sqrt(var) + 1e-8f);
    float m = (float)mean;
    for (int i = blockIdx.x * blockDim.x + threadIdx.x; i < n; i += gridDim.x * blockDim.x)
        g_inp[i] = (x[i] - m) * istd;
}

// ---------------- small setup kernels ----------------
__global__ void split_nnout_k() {
    int idx = blockIdx.x * blockDim.x + threadIdx.x;
    int total = BATCHD * 1600;
    if (idx >= total) return;
    int b = idx / 1600, r = idx % 1600;
    if (r < NVARD) g_lam[b * NVARD + r] = g_nnout[b * MLPOUTD + NVARD + r];
    else {
        int j = r - NVARD;
        g_s[b * NCD + j] = fmaxf(g_nnout[b * MLPOUTD + 2 * NVARD + j], 0.f);
    }
}

__global__ void transpose_C_k(const float* __restrict__ Cm) {
    int idx = blockIdx.x * blockDim.x + threadIdx.x;
    if (idx >= NVARD * NCD) return;
    int i = idx / NCD, k = idx % NCD;
    g_Ct[i * NCD + k] = Cm[k * NVARD + i];
}

__global__ void negg_k(const float* __restrict__ gv) {
    int j = blockIdx.x * blockDim.x + threadIdx.x;
    if (j < NVARD) g_negg[j] = -gv[j];
}

__global__ void init_G_k() {
    int idx = blockIdx.x * blockDim.x + threadIdx.x;
    if (idx >= KKTN * GLD) return;
    int r = idx / GLD, c = idx % GLD;
    float v = 0.f;
    if (c >= 750) {
        if (c - 750 == r) v = 1.f;
    } else if (r >= 600 && c < 600) {
        int rr = r - 600, t = rr / 3, i = rr % 3;
        if (c / 12 == t && (c % 12) % 3 == i) v = 1.f;
    } else if (r < 600 && c >= 600) {
        int cc = c - 600, t = cc / 3, i = cc % 3;
        if (r / 12 == t && (r % 12) % 3 == i) v = 1.f;
    }
    g_G[idx] = v;
}

__global__ void v0_k() {
    int j = blockIdx.x * blockDim.x + threadIdx.x;
    if (j >= NVARD) return;
    float beq = 30.0f * 9.81f;
    float acc = 0.f;
    for (int t = 0; t < 50; t++) acc += g_G[j * GLD + 750 + 600 + 3 * t + 2];
    g_v0[j] = beq * acc;
}

// ---------------- blocked Gauss-Jordan helpers ----------------
__global__ void copy_cols_k(int kb) {
    int idx = blockIdx.x * blockDim.x + threadIdx.x;
    if (idx >= KKTN * BLKD) return;
    int r = idx / BLKD, j = idx % BLKD;
    g_Ucol[r * BILD + j] = g_G[r * GLD + kb * BLKD + j];
}

__global__ void inv_block_k(int kb) {
    extern __shared__ float s[];
    const int n = BLKD, ld = BILD;
    int tid = threadIdx.x, nt = blockDim.x;
    for (int e = tid; e < n * n; e += nt)
        s[(e / n) * ld + (e % n)] = g_Ucol[(kb * BLKD + e / n) * BILD + (e % n)];
    __shared__ float fcol[BLKD];
    __shared__ float s_ipiv;
    __syncthreads();
    for (int p = 0; p < n; p++) {
        if (tid == 0) s_ipiv = 1.0f / s[p * ld + p];
        __syncthreads();
        float ipiv = s_ipiv;
        for (int j = tid; j < n; j += nt) if (j != p) s[p * ld + j] *= ipiv;
        for (int r = tid; r < n; r += nt) fcol[r] = (r == p) ? 0.f : s[r * ld + p];
        __syncthreads();
        for (int e = tid; e < n * n; e += nt) {
            int r = e / n, j = e % n;
            if (r != p && j != p) s[r * ld + j] -= fcol[r] * s[p * ld + j];
        }
        __syncthreads();
        for (int r = tid; r < n; r += nt) {
            if (r == p) s[p * ld + p] = ipiv;
            else s[r * ld + p] = -fcol[r] * ipiv;
        }
        __syncthreads();
    }
    for (int e = tid; e < n * n; e += nt)
        g_Einv[(e / n) * BILD + (e % n)] = s[(e / n) * ld + (e % n)];
}

__global__ void writeback_k(int kb) {
    int idx = blockIdx.x * blockDim.x + threadIdx.x;
    if (idx >= BLKD * GLD) return;
    int r = idx / GLD, j = idx % GLD;
    g_G[(kb * BLKD + r) * GLD + j] = g_P[idx];
    if (j < BILD) g_Ucol[(kb * BLKD + r) * BILD + j] = 0.f;
}

// ---------------- iteration elementwise kernels ----------------
__global__ void baug_k(const float* __restrict__ cvec) {
    int idx = blockIdx.x * blockDim.x + threadIdx.x;
    if (idx >= BATCHD * NCD) return;
    int j = idx % NCD;
    g_baug[idx] = cvec[j] - g_s[idx];
}

__global__ void rownorm_k(const float* __restrict__ v, int ncols, float* __restrict__ out) {
    int b = blockIdx.x;
    float acc = 0.f;
    for (int j = threadIdx.x; j < ncols; j += blockDim.x) {
        float t = v[b * ncols + j]; acc += t * t;
    }
    __shared__ float sm[256];
    sm[threadIdx.x] = acc; __syncthreads();
    for (int o = 128; o > 0; o >>= 1) {
        if (threadIdx.x < o) sm[threadIdx.x] += sm[threadIdx.x + o];
        __syncthreads();
    }
    if (threadIdx.x == 0) out[b] = sqrtf(sm[0]);
}

__global__ void concat_r_k() {
    int idx = blockIdx.x * blockDim.x + threadIdx.x;
    if (idx >= BATCHD * GIND) return;
    int b = idx / GIND, q = idx % GIND;
    float v;
    if (q < 1000)       v = g_s[b * NCD + q];
    else if (q < 1600)  v = g_lam[b * NVARD + (q - 1000)];
    else if (q < 2600)  v = g_snew[b * NCD + (q - 1600)];
    else if (q < 3200)  v = g_lamnew[b * NVARD + (q - 2600)];
    else if (q < 4200)  v = g_snew[b * NCD + (q - 3200)] - g_s[b * NCD + (q - 3200)];
    else                v = g_lamnew[b * NVARD + (q - 4200)] - g_lam[b * NVARD + (q - 4200)];
    g_r[idx] = v;
}

__device__ __forceinline__ float sigmoidf(float x) { return 1.0f / (1.0f + expf(-x)); }

__global__ void gru_k() {
    int idx = blockIdx.x * blockDim.x + threadIdx.x;
    if (idx >= BATCHD * HIDD) return;
    int b = idx >> 10, j = idx & 1023;
    int base = b * 3 * HIDD + j;
    float ir = g_gi[base], iz = g_gi[base + HIDD], in_ = g_gi[base + 2 * HIDD];
    float hr = g_gh[base], hz = g_gh[base + HIDD], hn = g_gh[base + 2 * HIDD];
    float rg = sigmoidf(ir + hr);
    float z  = sigmoidf(iz + hz);
    float n  = tanhf(in_ + rg * hn);
    float h  = g_hst[idx];
    g_hst[idx] = (1.f - z) * n + z * h;
}

__global__ void finalize_k(int t) {
    int b = blockIdx.x;
    float accs = 0.f, accl = 0.f;
    for (int j = threadIdx.x; j < GOUTD; j += blockDim.x) {
        float go = g_gout[b * GOUTD + j];
        if (j < NCD) {
            float sf = fmaxf(g_snew[b * NCD + j] + go, 0.f);
            float d = sf - g_s[b * NCD + j];
            accs += d * d;
            g_s[b * NCD + j] = sf;
        } else {
            int j2 = j - NCD;
            float lf = g_lamnew[b * NVARD + j2] + go;
            float d = lf - g_lam[b * NVARD + j2];
            accl += d * d;
            g_lam[b * NVARD + j2] = lf;
        }
    }
    __shared__ float sm1[256], sm2[256];
    sm1[threadIdx.x] = accs; sm2[threadIdx.x] = accl;
    __syncthreads();
    for (int o = 128; o > 0; o >>= 1) {
        if (threadIdx.x < o) { sm1[threadIdx.x] += sm1[threadIdx.x+o]; sm2[threadIdx.x] += sm2[threadIdx.x+o]; }
        __syncthreads();
    }
    if (threadIdx.x == 0)
        g_fp[t * BATCHD + b] = sqrtf(sm2[0]) + sqrtf(sm1[0]);
}

// ---------------- output assembly ----------------
__global__ void output_k(float* __restrict__ out) {
    int idx = blockIdx.x * blockDim.x + threadIdx.x;
    if (idx >= OUT_TOTAL) return;
    const int XI_END = BATCHD * NVARD;
    const int AFP_END = XI_END + BATCHD;
    const int APR_END = AFP_END + BATCHD;
    const int PH_END = APR_END + MAXITERD * BATCHD;
    if (idx < XI_END) out[idx] = g_xi[idx];
    else if (idx < AFP_END) {
        int b = idx - XI_END;
        float a = 0.f;
        for (int t = 0; t < MAXITERD; t++) a += g_fp[t * BATCHD + b];
        out[idx] = a / (float)MAXITERD;
    } else if (idx < APR_END) {
        int b = idx - AFP_END;
        float a = 0.f;
        for (int t = 0; t < MAXITERD; t++) a += g_prim[t * BATCHD + b];
        out[idx] = a / (float)MAXITERD;
    } else if (idx < PH_END) out[idx] = g_prim[idx - APR_END];
    else out[idx] = g_fp[idx - PH_END];
}

// ---------------- host side ----------------
static void gemm(const float* A, const float* B, float* C, float* C2,
                 const float* Cin, const float* bias,
                 int M, int N, int K, int lda, int ldb, int ldc, int ldcin,
                 int transB, float alpha, float beta, int act)
{
    dim3 grid((N + BN - 1) / BN, (M + BM - 1) / BM);
    gemm_k<<<grid, 256>>>(A, B, C, C2, Cin, bias, M, N, K, lda, ldb, ldc, ldcin,
                          transB, alpha, beta, act);
}

static void gemm_tc(const float* A, const float* B, float* C, float* C2,
                    const float* Cin, const float* bias,
                    int M, int N, int K, int lda, int ldb, int ldc, int ldcin,
                    int transB, float alpha, float beta, int act)
{
    long tiles128 = (long)((M + 127) / 128) * ((N + 127) / 128);
    if (M >= 128 && tiles128 >= 96) {
        dim3 grid((N + 127) / 128, (M + 127) / 128);
        gemm_tc_k<128, 128><<<grid, 256>>>(A, B, C, C2, Cin, bias, M, N, K,
                                           lda, ldb, ldc, ldcin, transB, alpha, beta, act);
    } else {
        dim3 grid((N + 63) / 64, (M + 63) / 64);
        gemm_tc_k<64, 64><<<grid, 256>>>(A, B, C, C2, Cin, bias, M, N, K,
                                         lda, ldb, ldc, ldcin, transB, alpha, beta, act);
    }
}

static inline int ceil_div(int a, int b) { return (a + b - 1) / b; }

extern "C" void kernel_launch(void* const* d_in, const int* in_sizes, int n_in,
                              void* d_out, int out_size) {
    const float* X    = (const float*)d_in[0];
    const float* Hm   = (const float*)d_in[1];
    const float* gv   = (const float*)d_in[2];
    const float* Cm   = (const float*)d_in[3];
    const float* cvec = (const float*)d_in[4];
    const float* W1   = (const float*)d_in[5];
    const float* b1   = (const float*)d_in[6];
    const float* W2   = (const float*)d_in[7];
    const float* b2   = (const float*)d_in[8];
    const float* W3   = (const float*)d_in[9];
    const float* b3   = (const float*)d_in[10];
    const float* Wg   = (const float*)d_in[11];
    const float* bg   = (const float*)d_in[12];
    const float* W_ih = (const float*)d_in[13];
    const float* W_hh = (const float*)d_in[14];
    const float* b_ih = (const float*)d_in[15];
    const float* b_hh = (const float*)d_in[16];
    const float* W_out= (const float*)d_in[17];
    const float* b_out= (const float*)d_in[18];
    float* out = (float*)d_out;

    float *inp, *h1, *h2, *nnout, *hst, *lam, *lamnew, *s, *snew, *res, *baug, *u, *xi,
          *r, *gi, *gh, *gout, *G, *P, *Ucol, *Einv, *Ct, *v0, *negg, *prim, *fp;
    cudaGetSymbolAddress((void**)&inp, g_inp);
    cudaGetSymbolAddress((void**)&h1, g_h1);
    cudaGetSymbolAddress((void**)&h2, g_h2);
    cudaGetSymbolAddress((void**)&nnout, g_nnout);
    cudaGetSymbolAddress((void**)&hst, g_hst);
    cudaGetSymbolAddress((void**)&lam, g_lam);
    cudaGetSymbolAddress((void**)&lamnew, g_lamnew);
    cudaGetSymbolAddress((void**)&s, g_s);
    cudaGetSymbolAddress((void**)&snew, g_snew);
    cudaGetSymbolAddress((void**)&res, g_res);
    cudaGetSymbolAddress((void**)&baug, g_baug);
    cudaGetSymbolAddress((void**)&u, g_u);
    cudaGetSymbolAddress((void**)&xi, g_xi);
    cudaGetSymbolAddress((void**)&r, g_r);
    cudaGetSymbolAddress((void**)&gi, g_gi);
    cudaGetSymbolAddress((void**)&gh, g_gh);
    cudaGetSymbolAddress((void**)&gout, g_gout);
    cudaGetSymbolAddress((void**)&G, g_G);
    cudaGetSymbolAddress((void**)&P, g_P);
    cudaGetSymbolAddress((void**)&Ucol, g_Ucol);
    cudaGetSymbolAddress((void**)&Einv, g_Einv);
    cudaGetSymbolAddress((void**)&Ct, g_Ct);
    cudaGetSymbolAddress((void**)&v0, g_v0);
    cudaGetSymbolAddress((void**)&negg, g_negg);
    cudaGetSymbolAddress((void**)&prim, g_prim);
    cudaGetSymbolAddress((void**)&fp, g_fp);

    cudaFuncSetAttribute(inv_block_k, cudaFuncAttributeMaxDynamicSharedMemorySize,
                         BLKD * BILD * (int)sizeof(float));

    const int TPB = 256;
    const int NTOT = BATCHD * NVARD;

    // ---- input normalization ----
    stats_zero_k<<<1, 1>>>();
    stats_k<<<512, TPB>>>(X, NTOT);
    normalize_k<<<ceil_div(NTOT, TPB), TPB>>>(X, NTOT);

    // ---- MLP warm start (tensor cores) ----
    gemm_tc(inp, W1, h1, nullptr, nullptr, b1, BATCHD, HIDD, NVARD, NVARD, NVARD, HIDD, 0, 1, 1.f, 0.f, 1);
    gemm_tc(h1, W2, h2, nullptr, nullptr, b2, BATCHD, HIDD, HIDD, HIDD, HIDD, HIDD, 0, 1, 1.f, 0.f, 1);
    gemm_tc(h2, W3, nnout, nullptr, nullptr, b3, BATCHD, MLPOUTD, HIDD, HIDD, HIDD, MLPOUTD, 0, 1, 1.f, 0.f, 0);
    split_nnout_k<<<ceil_div(BATCHD * 1600, TPB), TPB>>>();
    gemm_tc(inp, Wg, hst, nullptr, nullptr, bg, BATCHD, HIDD, NVARD, NVARD, NVARD, HIDD, 0, 1, 1.f, 0.f, 2);

    // ---- KKT build + blocked Gauss-Jordan inverse (fp32 SIMT) ----
    transpose_C_k<<<ceil_div(NVARD * NCD, TPB), TPB>>>(Cm);
    negg_k<<<ceil_div(NVARD, TPB), TPB>>>(gv);
    init_G_k<<<ceil_div(KKTN * GLD, TPB), TPB>>>();
    gemm(Ct, Ct, G, nullptr, Hm, nullptr, NVARD, NVARD, NCD, NCD, NCD, GLD, NVARD, 1, 1.f, 1.f, 0);
    for (int kb = 0; kb < KKTN / BLKD; kb++) {
        copy_cols_k<<<ceil_div(KKTN * BLKD, TPB), TPB>>>(kb);
        inv_block_k<<<1, 1024, BLKD * BILD * sizeof(float)>>>(kb);
        gemm(Einv, G + kb * BLKD * GLD, P, nullptr, nullptr, nullptr,
             BLKD, GLD, BLKD, BILD, GLD, GLD, 0, 0, 1.f, 0.f, 0);
        writeback_k<<<ceil_div(BLKD * GLD, TPB), TPB>>>(kb);
        gemm(Ucol, P, G, nullptr, G, nullptr,
             KKTN, GLD, BLKD, BILD, GLD, GLD, GLD, 0, -1.f, 1.f, 0);
    }
    v0_k<<<ceil_div(NVARD, TPB), TPB>>>();

    const float* Minv = G + 750;

    // ---- 15 fixed-point iterations ----
    for (int t = 0; t < MAXITERD; t++) {
        baug_k<<<ceil_div(BATCHD * NCD, TPB), TPB>>>(cvec);
        gemm_tc(baug, Cm, u, nullptr, lam, negg, BATCHD, NVARD, NCD, NCD, NVARD, NVARD, NVARD, 0, 1.f, 1.f, 0);
        gemm_tc(u, Minv, xi, nullptr, nullptr, v0, BATCHD, NVARD, NVARD, NVARD, GLD, NVARD, 0, 0, 1.f, 0.f, 0);
        gemm_tc(xi, Cm, snew, res, nullptr, cvec, BATCHD, NCD, NVARD, NVARD, NVARD, NCD, 0, 1, 1.f, 0.f, 3);
        rownorm_k<<<BATCHD, 256>>>(res, NCD, prim + t * BATCHD);
        gemm_tc(res, Cm, lamnew, nullptr, lam, nullptr, BATCHD, NVARD, NCD, NCD, NVARD, NVARD, NVARD, 0, -1.f, 1.f, 0);
        concat_r_k<<<ceil_div(BATCHD * GIND, TPB), TPB>>>();
        gemm_tc(r, W_ih, gi, nullptr, nullptr, b_ih, BATCHD, 3 * HIDD, GIND, GIND, GIND, 3 * HIDD, 0, 1, 1.f, 0.f, 0);
        gemm_tc(hst, W_hh, gh, nullptr, nullptr, b_hh, BATCHD, 3 * HIDD, HIDD, HIDD, HIDD, 3 * HIDD, 0, 1, 1.f, 0.f, 0);
        gru_k<<<ceil_div(BATCHD * HIDD, TPB), TPB>>>();
        gemm_tc(hst, W_out, gout, nullptr, nullptr, b_out, BATCHD, GOUTD, HIDD, HIDD, HIDD, GOUTD, 0, 1, 1.f, 0.f, 0);
        finalize_k<<<BATCHD, 256>>>(t);
    }

    output_k<<<ceil_div(OUT_TOTAL, TPB), TPB>>>(out);
    (void)in_sizes; (void)n_in; (void)out_size;
}